// round 1
// baseline (speedup 1.0000x reference)
#include <cuda_runtime.h>

#define N 6000
#define NMS_TH 0.7f
#define MAX_E (4u << 20)
#define TI 128
#define CH 256
#define NCH 24   // ceil(6000/256) = 24 chunks

// ---------------- device scratch (no allocations allowed) ----------------
__device__ float         g_boxes_s[N * 6];   // sorted boxes
__device__ float         g_scores_s[N];      // sorted scores
__device__ float         g_aux[N * 4];       // area, cx, cy, cz per sorted box
__device__ unsigned int  g_edges[MAX_E];     // packed (i<<16)|j, i<j, diou>=0.7
__device__ int           g_ecount;
__device__ unsigned char g_mask[N];          // final keep mask
__device__ float         g_partial[N * NCH * 8]; // per (row, chunk): acc[6], wsum, pad

// ---------------- K1: stable descending rank sort + scatter ----------------
__global__ void k_rank(const float* __restrict__ boxes,
                       const float* __restrict__ scores) {
    __shared__ float ss[N];
    int tx = threadIdx.x;
    for (int j = tx; j < N; j += blockDim.x) ss[j] = scores[j];
    __syncthreads();

    int gid = blockIdx.x * blockDim.x + tx;
    if (gid == 0) g_ecount = 0;
    if (gid >= N) return;

    float s = ss[gid];
    int c = 0;
#pragma unroll 8
    for (int j = 0; j < N; j++) {
        float t = ss[j];
        c += (t > s) || (t == s && j < gid);
    }
    float x1 = boxes[gid * 6 + 0], y1 = boxes[gid * 6 + 1];
    float x2 = boxes[gid * 6 + 2], y2 = boxes[gid * 6 + 3];
    float z1 = boxes[gid * 6 + 4], z2 = boxes[gid * 6 + 5];
    g_boxes_s[c * 6 + 0] = x1; g_boxes_s[c * 6 + 1] = y1;
    g_boxes_s[c * 6 + 2] = x2; g_boxes_s[c * 6 + 3] = y2;
    g_boxes_s[c * 6 + 4] = z1; g_boxes_s[c * 6 + 5] = z2;
    g_scores_s[c] = s;
    g_aux[c * 4 + 0] = (x2 - x1) * (y2 - y1) * (z2 - z1);
    g_aux[c * 4 + 1] = (x2 + x1) * 0.5f;
    g_aux[c * 4 + 2] = (y2 + y1) * 0.5f;
    g_aux[c * 4 + 3] = (z1 + z2) * 0.5f;
}

// ---------------- K2: all-pairs DIoU >= 0.7 edge extraction ----------------
__global__ void k_edges() {
    int j0 = blockIdx.x * 256;
    int i0 = blockIdx.y * TI;
    if (i0 > j0 + 254) return;   // no i < j in this tile

    __shared__ float sb[TI * 6];
    __shared__ float sa[TI * 4];
    int tx = threadIdx.x;
    for (int idx = tx; idx < TI * 6; idx += 256) {
        int i = i0 + idx / 6;
        sb[idx] = (i < N) ? g_boxes_s[i0 * 6 + idx] : 0.0f;
    }
    for (int idx = tx; idx < TI * 4; idx += 256) {
        int i = i0 + idx / 4;
        sa[idx] = (i < N) ? g_aux[i0 * 4 + idx] : 0.0f;
    }
    __syncthreads();

    int j = j0 + tx;
    if (j >= N) return;
    float bx1 = g_boxes_s[j * 6 + 0], by1 = g_boxes_s[j * 6 + 1];
    float bx2 = g_boxes_s[j * 6 + 2], by2 = g_boxes_s[j * 6 + 3];
    float bz1 = g_boxes_s[j * 6 + 4], bz2 = g_boxes_s[j * 6 + 5];
    float barea = g_aux[j * 4 + 0];
    float bcx = g_aux[j * 4 + 1], bcy = g_aux[j * 4 + 2], bcz = g_aux[j * 4 + 3];

    int ilim = j - i0;                 // need i < j
    if (ilim > TI) ilim = TI;
    for (int ii = 0; ii < ilim; ii++) {
        float ax1 = sb[ii * 6 + 0], ax2 = sb[ii * 6 + 2];
        float iw = fminf(ax2, bx2) - fmaxf(ax1, bx1);
        if (iw <= 0.0f) continue;
        float ay1 = sb[ii * 6 + 1], ay2 = sb[ii * 6 + 3];
        float ih = fminf(ay2, by2) - fmaxf(ay1, by1);
        if (ih <= 0.0f) continue;
        float az1 = sb[ii * 6 + 4], az2 = sb[ii * 6 + 5];
        float dp = fminf(az2, bz2) - fmaxf(az1, bz1);
        if (dp <= 0.0f) continue;

        float inter = iw * ih * dp;
        float uni = sa[ii * 4 + 0] + barea - inter + 1e-7f;
        float dx = bcx - sa[ii * 4 + 1];
        float dy = bcy - sa[ii * 4 + 2];
        float dz = bcz - sa[ii * 4 + 3];
        float idiag = dx * dx + dy * dy + dz * dz;
        float ow = fmaxf(ax2, bx2) - fminf(ax1, bx1);
        float oh = fmaxf(ay2, by2) - fminf(ay1, by1);
        float od = fmaxf(az2, bz2) - fminf(az1, bz1);
        float odiag = ow * ow + oh * oh + od * od + 1e-7f;
        float v = inter / uni - idiag / odiag;
        if (v >= NMS_TH) {
            unsigned e = atomicAdd(&g_ecount, 1);
            if (e < MAX_E)
                g_edges[e] = ((unsigned)(i0 + ii) << 16) | (unsigned)j;
        }
    }
}

// ---------------- K3: fixed-point mask iteration on edge list ----------------
__global__ void k_iter() {
    __shared__ unsigned char smask[N];
    __shared__ unsigned char ssup[N];
    int tx = threadIdx.x;
    for (int j = tx; j < N; j += 1024) smask[j] = 1;
    int E = g_ecount;
    if (E > (int)MAX_E) E = MAX_E;
    __syncthreads();

    for (int t = 0; t < 200; t++) {
        for (int j = tx; j < N; j += 1024) ssup[j] = 0;
        __syncthreads();
        for (int e = tx; e < E; e += 1024) {
            unsigned p = g_edges[e];
            int i = p >> 16, j = p & 0xFFFF;
            if (smask[i]) ssup[j] = 1;
        }
        __syncthreads();
        int change = 0;
        for (int j = tx; j < N; j += 1024) {
            unsigned char nm = ssup[j] ? 0 : 1;
            if (nm != smask[j]) change = 1;
            smask[j] = nm;
        }
        if (!__syncthreads_or(change)) break;
    }
    for (int j = tx; j < N; j += 1024) g_mask[j] = smask[j];
}

// ---------------- K4: per-row weighted merge partials (deterministic) ----------------
__global__ void k_merge() {
    int rb = blockIdx.x, c = blockIdx.y;
    if (c < rb) return;   // chunk entirely at j <= i for every row in block

    __shared__ float sj[CH * 12];  // per j: box[6], score, area, cx, cy, cz
    int tx = threadIdx.x;
    {
        int j = c * CH + tx;
        if (j < N) {
            sj[tx * 12 + 0] = g_boxes_s[j * 6 + 0];
            sj[tx * 12 + 1] = g_boxes_s[j * 6 + 1];
            sj[tx * 12 + 2] = g_boxes_s[j * 6 + 2];
            sj[tx * 12 + 3] = g_boxes_s[j * 6 + 3];
            sj[tx * 12 + 4] = g_boxes_s[j * 6 + 4];
            sj[tx * 12 + 5] = g_boxes_s[j * 6 + 5];
            sj[tx * 12 + 6] = g_scores_s[j];
            sj[tx * 12 + 7] = g_aux[j * 4 + 0];
            sj[tx * 12 + 8] = g_aux[j * 4 + 1];
            sj[tx * 12 + 9] = g_aux[j * 4 + 2];
            sj[tx * 12 + 10] = g_aux[j * 4 + 3];
        }
    }
    __syncthreads();

    int i = rb * 256 + tx;
    float a0 = 0, a1 = 0, a2 = 0, a3 = 0, a4 = 0, a5 = 0, w = 0;
    if (i < N && g_mask[i]) {
        float ax1 = g_boxes_s[i * 6 + 0], ay1 = g_boxes_s[i * 6 + 1];
        float ax2 = g_boxes_s[i * 6 + 2], ay2 = g_boxes_s[i * 6 + 3];
        float az1 = g_boxes_s[i * 6 + 4], az2 = g_boxes_s[i * 6 + 5];
        float aarea = g_aux[i * 4 + 0];
        float acx = g_aux[i * 4 + 1], acy = g_aux[i * 4 + 2], acz = g_aux[i * 4 + 3];

        int jj0 = i + 1 - c * CH;
        if (jj0 < 0) jj0 = 0;
        int jje = N - c * CH;
        if (jje > CH) jje = CH;
        for (int jj = jj0; jj < jje; jj++) {
            float bx1 = sj[jj * 12 + 0], bx2 = sj[jj * 12 + 2];
            float iw = fminf(ax2, bx2) - fmaxf(ax1, bx1);
            if (iw <= 0.0f) continue;
            float by1 = sj[jj * 12 + 1], by2 = sj[jj * 12 + 3];
            float ih = fminf(ay2, by2) - fmaxf(ay1, by1);
            if (ih <= 0.0f) continue;
            float bz1 = sj[jj * 12 + 4], bz2 = sj[jj * 12 + 5];
            float dp = fminf(az2, bz2) - fmaxf(az1, bz1);
            if (dp <= 0.0f) continue;

            float inter = iw * ih * dp;
            float uni = aarea + sj[jj * 12 + 7] - inter + 1e-7f;
            float dx = sj[jj * 12 + 8] - acx;
            float dy = sj[jj * 12 + 9] - acy;
            float dz = sj[jj * 12 + 10] - acz;
            float idiag = dx * dx + dy * dy + dz * dz;
            float ow = fmaxf(ax2, bx2) - fminf(ax1, bx1);
            float oh = fmaxf(ay2, by2) - fminf(ay1, by1);
            float od = fmaxf(az2, bz2) - fminf(az1, bz1);
            float odiag = ow * ow + oh * oh + od * od + 1e-7f;
            float v = inter / uni - idiag / odiag;
            if (v > NMS_TH) {                 // strict > for weights
                float wt = v * sj[jj * 12 + 6];
                w += wt;
                a0 += wt * bx1; a1 += wt * by1; a2 += wt * bx2;
                a3 += wt * by2; a4 += wt * bz1; a5 += wt * bz2;
            }
        }
    }
    if (i < N) {
        float* p = &g_partial[(i * NCH + c) * 8];
        p[0] = a0; p[1] = a1; p[2] = a2;
        p[3] = a3; p[4] = a4; p[5] = a5; p[6] = w;
    }
}

// ---------------- K5: combine partials, write outputs ----------------
__global__ void k_final(float* __restrict__ out) {
    int i = blockIdx.x * blockDim.x + threadIdx.x;
    if (i >= N) return;
    float s = g_scores_s[i];
    float acc[6];
#pragma unroll
    for (int k = 0; k < 6; k++) acc[k] = s * g_boxes_s[i * 6 + k];
    float wsum = s;
    for (int c = i >> 8; c < NCH; c++) {
        const float* p = &g_partial[(i * NCH + c) * 8];
#pragma unroll
        for (int k = 0; k < 6; k++) acc[k] += p[k];
        wsum += p[6];
    }
#pragma unroll
    for (int k = 0; k < 6; k++) out[i * 6 + k] = acc[k] / wsum;
    out[N * 6 + i] = g_mask[i] ? 1.0f : 0.0f;   // keep
    out[N * 7 + i] = s;                          // scores_s
}

// ---------------- launch ----------------
extern "C" void kernel_launch(void* const* d_in, const int* in_sizes, int n_in,
                              void* d_out, int out_size) {
    const float* boxes = (const float*)d_in[0];
    const float* scores = (const float*)d_in[1];
    float* out = (float*)d_out;

    k_rank<<<24, 256>>>(boxes, scores);
    dim3 g2(24, (N + TI - 1) / TI);
    k_edges<<<g2, 256>>>();
    k_iter<<<1, 1024>>>();
    dim3 g4(24, NCH);
    k_merge<<<g4, 256>>>();
    k_final<<<24, 256>>>(out);
}

// round 2
// speedup vs baseline: 3.6778x; 3.6778x over previous
#include <cuda_runtime.h>

#define N 6000
#define NMS_TH 0.7f
#define MAX_E (1 << 20)
#define IT 128
#define NT 47        // ceil(6000/128)

// ---------------- device scratch ----------------
__device__ float4        g_filt[NT * IT];        // cx, cy, cz, R2 (sorted order)
__device__ float         g_full[N * 8];          // x1,y1,x2,y2,z1,z2,area,score (sorted)
__device__ int           g_rank[N];
__device__ int           g_rowcnt[N];
__device__ int           g_rowoff[N + 1];
__device__ int           g_fill[N];
__device__ unsigned int  g_eij[MAX_E];           // (i<<16)|j, i<j
__device__ float         g_ev[MAX_E];            // DIoU value
__device__ int           g_csrj[MAX_E];
__device__ float         g_csrv[MAX_E];
__device__ int           g_ecount;
__device__ unsigned char g_mask[N];

// ---------------- K0: zero counters ----------------
__global__ void k_zero() {
    int i = blockIdx.x * 1024 + threadIdx.x;
    if (i < N) { g_rank[i] = 0; g_rowcnt[i] = 0; }
    if (i == 0) g_ecount = 0;
}

// ---------------- K1: partial rank counts (2D split, int atomics) ----------------
__global__ void k_rank_count(const float* __restrict__ scores) {
    __shared__ float ss[1000];
    int tx = threadIdx.x;
    int j0 = blockIdx.y * 1000;
    for (int jj = tx; jj < 1000; jj += 256) ss[jj] = scores[j0 + jj];
    __syncthreads();

    int i = blockIdx.x * 256 + tx;
    if (i >= N) return;
    float s = scores[i];
    int c = 0;
#pragma unroll 4
    for (int jj = 0; jj < 1000; jj++) {
        float t = ss[jj];
        c += (t > s) || (t == s && (j0 + jj) < i);
    }
    atomicAdd(&g_rank[i], c);
}

// ---------------- K2: scatter into sorted order + precompute ----------------
__global__ void k_scatter(const float* __restrict__ boxes,
                          const float* __restrict__ scores) {
    int gid = blockIdx.x * 256 + threadIdx.x;
    // init padding for filter tiles
    if (gid >= N && gid < NT * IT) g_filt[gid] = make_float4(1e30f, 1e30f, 1e30f, 0.0f);
    if (gid >= N) return;

    int c = g_rank[gid];
    float x1 = boxes[gid * 6 + 0], y1 = boxes[gid * 6 + 1];
    float x2 = boxes[gid * 6 + 2], y2 = boxes[gid * 6 + 3];
    float z1 = boxes[gid * 6 + 4], z2 = boxes[gid * 6 + 5];
    float s = scores[gid];
    g_full[c * 8 + 0] = x1; g_full[c * 8 + 1] = y1;
    g_full[c * 8 + 2] = x2; g_full[c * 8 + 3] = y2;
    g_full[c * 8 + 4] = z1; g_full[c * 8 + 5] = z2;
    g_full[c * 8 + 6] = (x2 - x1) * (y2 - y1) * (z2 - z1);
    g_full[c * 8 + 7] = s;
    float cx = (x2 + x1) * 0.5f, cy = (y2 + y1) * 0.5f, cz = (z1 + z2) * 0.5f;
    float rx = (x2 - x1) * 0.5f, ry = (y2 - y1) * 0.5f, rz = (z2 - z1) * 0.5f;
    float R2 = 0.36f * (rx * rx + ry * ry + rz * rz);
    R2 = R2 * 1.002f + 1e-3f;   // margin against fp rounding (necessary-condition filter)
    g_filt[c] = make_float4(cx, cy, cz, R2);
}

// ---------------- K3: edge extraction with sphere prefilter ----------------
__global__ void k_edges() {
    int j0 = blockIdx.x * IT;
    int i0 = blockIdx.y * IT;
    if (i0 >= j0 + IT) return;   // no i < j possible

    __shared__ float4 sfilt[IT];
    __shared__ float  sfull[IT * 8];
    int tx = threadIdx.x;
    sfilt[tx] = g_filt[i0 + tx];   // padded region valid (1e30 centers)
    {
        int ig = i0 + tx;
#pragma unroll
        for (int k = 0; k < 8; k++)
            sfull[tx * 8 + k] = (ig < N) ? g_full[ig * 8 + k] : 0.0f;
    }
    __syncthreads();

    int j = j0 + tx;
    if (j >= N) return;
    float4 bf = g_filt[j];
    float bx1 = g_full[j * 8 + 0], by1 = g_full[j * 8 + 1];
    float bx2 = g_full[j * 8 + 2], by2 = g_full[j * 8 + 3];
    float bz1 = g_full[j * 8 + 4], bz2 = g_full[j * 8 + 5];
    float barea = g_full[j * 8 + 6];

#pragma unroll 2
    for (int ii = 0; ii < IT; ii++) {
        float4 f = sfilt[ii];
        float dx = bf.x - f.x, dy = bf.y - f.y, dz = bf.z - f.z;
        float d2 = dx * dx + dy * dy + dz * dz;
        if (d2 <= fminf(f.w, bf.w) && (i0 + ii) < j) {
            float ax1 = sfull[ii * 8 + 0], ay1 = sfull[ii * 8 + 1];
            float ax2 = sfull[ii * 8 + 2], ay2 = sfull[ii * 8 + 3];
            float az1 = sfull[ii * 8 + 4], az2 = sfull[ii * 8 + 5];
            float iw = fminf(ax2, bx2) - fmaxf(ax1, bx1);
            float ih = fminf(ay2, by2) - fmaxf(ay1, by1);
            float dp = fminf(az2, bz2) - fmaxf(az1, bz1);
            if (iw > 0.0f && ih > 0.0f && dp > 0.0f) {
                float inter = iw * ih * dp;
                float uni = sfull[ii * 8 + 6] + barea - inter + 1e-7f;
                float idiag = dx * dx + dy * dy + dz * dz;
                float ow = fmaxf(ax2, bx2) - fminf(ax1, bx1);
                float oh = fmaxf(ay2, by2) - fminf(ay1, by1);
                float od = fmaxf(az2, bz2) - fminf(az1, bz1);
                float odiag = ow * ow + oh * oh + od * od + 1e-7f;
                float v = inter / uni - idiag / odiag;
                if (v >= NMS_TH) {
                    int e = atomicAdd(&g_ecount, 1);
                    if (e < MAX_E) {
                        g_eij[e] = ((unsigned)(i0 + ii) << 16) | (unsigned)j;
                        g_ev[e] = v;
                        atomicAdd(&g_rowcnt[i0 + ii], 1);
                    }
                }
            }
        }
    }
}

// ---------------- K4: CSR build + sort + fixed-point iteration (1 block) ----------------
__global__ void k_post() {
    __shared__ int sp[1024];
    __shared__ unsigned char smask[N];
    __shared__ unsigned char ssup[N];
    int t = threadIdx.x;

    // ---- offsets: chunked exclusive scan over g_rowcnt ----
    int base = t * 6;
    int local = 0;
#pragma unroll
    for (int k = 0; k < 6; k++) {
        int idx = base + k;
        if (idx < N) local += g_rowcnt[idx];
    }
    sp[t] = local;
    __syncthreads();
    for (int off = 1; off < 1024; off <<= 1) {
        int v = sp[t];
        int add = (t >= off) ? sp[t - off] : 0;
        __syncthreads();
        sp[t] = v + add;
        __syncthreads();
    }
    int run = sp[t] - local;   // exclusive prefix of this chunk
#pragma unroll
    for (int k = 0; k < 6; k++) {
        int idx = base + k;
        if (idx < N) {
            g_rowoff[idx] = run;
            g_fill[idx] = run;
            run += g_rowcnt[idx];
        }
    }
    if (t == 1023) g_rowoff[N] = sp[1023];
    __syncthreads();

    int E = g_ecount;
    if (E > MAX_E) E = MAX_E;

    // ---- fill CSR ----
    for (int e = t; e < E; e += 1024) {
        unsigned p = g_eij[e];
        int i = p >> 16;
        int pos = atomicAdd(&g_fill[i], 1);
        g_csrj[pos] = (int)(p & 0xFFFF);
        g_csrv[pos] = g_ev[e];
    }
    __syncthreads();

    // ---- per-row insertion sort by j (determinism) ----
    for (int i = t; i < N; i += 1024) {
        int s0 = g_rowoff[i], s1 = g_rowoff[i + 1];
        for (int a = s0 + 1; a < s1; a++) {
            int jv = g_csrj[a]; float vv = g_csrv[a];
            int b = a - 1;
            while (b >= s0 && g_csrj[b] > jv) {
                g_csrj[b + 1] = g_csrj[b];
                g_csrv[b + 1] = g_csrv[b];
                b--;
            }
            g_csrj[b + 1] = jv;
            g_csrv[b + 1] = vv;
        }
    }

    // ---- fixed-point mask iteration on flat edge list ----
    for (int i = t; i < N; i += 1024) smask[i] = 1;
    __syncthreads();
    for (int it = 0; it < 200; it++) {
        for (int i = t; i < N; i += 1024) ssup[i] = 0;
        __syncthreads();
        for (int e = t; e < E; e += 1024) {
            unsigned p = g_eij[e];
            if (smask[p >> 16]) ssup[p & 0xFFFF] = 1;
        }
        __syncthreads();
        int change = 0;
        for (int i = t; i < N; i += 1024) {
            unsigned char nm = ssup[i] ? 0 : 1;
            if (nm != smask[i]) change = 1;
            smask[i] = nm;
        }
        if (!__syncthreads_or(change)) break;
    }
    for (int i = t; i < N; i += 1024) g_mask[i] = smask[i];
}

// ---------------- K5: merge from CSR + write outputs ----------------
__global__ void k_final(float* __restrict__ out) {
    int i = blockIdx.x * 256 + threadIdx.x;
    if (i >= N) return;
    float s = g_full[i * 8 + 7];
    float acc[6];
#pragma unroll
    for (int k = 0; k < 6; k++) acc[k] = s * g_full[i * 8 + k];
    float w = s;
    unsigned char m = g_mask[i];
    if (m) {
        int s0 = g_rowoff[i], s1 = g_rowoff[i + 1];
        for (int e = s0; e < s1; e++) {
            float v = g_csrv[e];
            if (v > NMS_TH) {           // strict > for merge weights
                int j = g_csrj[e];
                float wt = v * g_full[j * 8 + 7];
                w += wt;
#pragma unroll
                for (int k = 0; k < 6; k++) acc[k] += wt * g_full[j * 8 + k];
            }
        }
    }
#pragma unroll
    for (int k = 0; k < 6; k++) out[i * 6 + k] = acc[k] / w;
    out[N * 6 + i] = m ? 1.0f : 0.0f;
    out[N * 7 + i] = s;
}

// ---------------- launch ----------------
extern "C" void kernel_launch(void* const* d_in, const int* in_sizes, int n_in,
                              void* d_out, int out_size) {
    const float* boxes = (const float*)d_in[0];
    const float* scores = (const float*)d_in[1];
    float* out = (float*)d_out;

    k_zero<<<6, 1024>>>();
    k_rank_count<<<dim3(24, 6), 256>>>(scores);
    k_scatter<<<24, 256>>>(boxes, scores);
    k_edges<<<dim3(NT, NT), IT>>>();
    k_post<<<1, 1024>>>();
    k_final<<<24, 256>>>(out);
}